// round 2
// baseline (speedup 1.0000x reference)
#include <cuda_runtime.h>
#include <math.h>

// Problem constants (from reference)
#define LEVELS 3
#define BINS 9
#define NATOMS 51
#define ADIM 6
#define NB 4096
#define ROWS (LEVELS * ADIM * BINS)      // 162 rows per batch element
#define SLAB (ROWS * NATOMS)             // 8262 floats per batch element
#define V_MIN_C (-10.0f)
#define V_MAX_C (10.0f)
#define DZ_C (0.4f)                      // (V_MAX - V_MIN)/(ATOMS-1)

#define THREADS 256

__global__ __launch_bounds__(THREADS)
void c2f_kernel(const float* __restrict__ q,        // [B, L, A, BINS, ATOMS]
                const float* __restrict__ reward,    // [B, 1]
                const float* __restrict__ discount,  // [B, 1]
                const float* __restrict__ act,       // [B, ADIM]
                const float* __restrict__ support,   // [ATOMS]
                const float* __restrict__ low0,      // [ADIM]
                const float* __restrict__ high0,     // [ADIM]
                float* __restrict__ out)             // [B*SLAB] proj ++ [B*ADIM] decoded
{
    const int b = blockIdx.x;
    const int t = threadIdx.x;

    __shared__ float sp[SLAB];          // staged prob slab for this batch element
    __shared__ float swl[NATOMS];       // weight to atom 'lower'
    __shared__ float swu[NATOMS];       // weight to atom 'lower+1'
    __shared__ int   slower[NATOMS];
    __shared__ int   sstart[NATOMS + 1]; // start[k] = #{j : lower[j] < k}, k=0..51

    // ---- Phase 0: coalesced stage of the whole slab (8262 floats, even -> float2) ----
    {
        const float2* src2 = reinterpret_cast<const float2*>(q + (size_t)b * SLAB);
        float2* sp2 = reinterpret_cast<float2*>(sp);
        #pragma unroll 4
        for (int i = t; i < SLAB / 2; i += THREADS) sp2[i] = src2[i];
    }

    // ---- Phase 1a: per-atom projection coefficients (depend only on r, d, support) ----
    if (t < NATOMS) {
        const float r = reward[b];
        const float d = discount[b];
        const float z = support[t];
        float Tz = fminf(fmaxf(r + d * z, V_MIN_C), V_MAX_C);
        float bc = (Tz - V_MIN_C) / DZ_C;
        int lo = (int)floorf(bc);
        int up = (int)ceilf(bc);
        // sequential fixups exactly as reference (result: up == lo + 1 always)
        if (up > 0 && lo == up) lo -= 1;
        if (lo < NATOMS - 1 && lo == up) up += 1;
        slower[t] = lo;
        swl[t] = (float)up - bc;   // mass -> atom lo
        swu[t] = bc - (float)lo;   // mass -> atom up (= lo+1)
    }

    // ---- Phase 1b (parallel warp): encode + decode for this batch's 6 action dims ----
    if (t >= 64 && t < 64 + ADIM) {
        const int dim = t - 64;
        const float a = act[b * ADIM + dim];
        float low = low0[dim], high = high0[dim];
        float idx[LEVELS];
        #pragma unroll
        for (int lvl = 0; lvl < LEVELS; lvl++) {
            float sr = (high - low) / (float)BINS;
            float id = floorf((a - low) / sr);
            id = fminf(fmaxf(id, 0.0f), (float)(BINS - 1));
            float na = fminf(fmaxf(low + sr * id, -1.0f), 1.0f);
            low  = fmaxf(-1.0f, na);
            high = fminf(1.0f, na + sr);
            idx[lvl] = id;
        }
        // decode with the stored indices
        low = low0[dim]; high = high0[dim];
        #pragma unroll
        for (int lvl = 0; lvl < LEVELS; lvl++) {
            float sr = (high - low) / (float)BINS;
            float cont = low + sr * idx[lvl];
            low  = fmaxf(-1.0f, cont);
            high = fminf(1.0f, cont + sr);
        }
        out[(size_t)NB * SLAB + (size_t)b * ADIM + dim] = 0.5f * (high + low);
    }
    __syncthreads();

    // ---- Phase 1c: range table. lower[] is nondecreasing (discount >= 0), so
    //      {j : lower[j] == k} == [start[k], start[k+1]). 52 threads, 51 iters each.
    if (t < NATOMS + 1) {
        int cnt = 0;
        for (int j = 0; j < NATOMS; j++) cnt += (slower[j] < t) ? 1 : 0;
        sstart[t] = cnt;
    }
    __syncthreads();

    // ---- Phase 2: gather-form projection. out[row][k] =
    //   sum_{j: lower[j]==k}   p[row][j]*wl[j]      (range [start[k],   start[k+1]))
    // + sum_{j: lower[j]==k-1} p[row][j]*wu[j]      (range [start[k-1], start[k]))
    {
        float* dst = out + (size_t)b * SLAB;
        for (int e = t; e < SLAB; e += THREADS) {
            const int row = e / NATOMS;          // mul-shift
            const int k = e - row * NATOMS;
            const float* pr = sp + row * NATOMS;
            const int s0 = sstart[k];
            const int s1 = sstart[k + 1];
            float acc = 0.0f;
            for (int j = s0; j < s1; j++) acc = fmaf(pr[j], swl[j], acc);
            if (k > 0) {
                const int sm1 = sstart[k - 1];
                for (int j = sm1; j < s0; j++) acc = fmaf(pr[j], swu[j], acc);
            }
            dst[e] = acc;
        }
    }
}

extern "C" void kernel_launch(void* const* d_in, const int* in_sizes, int n_in,
                              void* d_out, int out_size)
{
    const float* q        = (const float*)d_in[0];
    const float* reward   = (const float*)d_in[1];
    const float* discount = (const float*)d_in[2];
    const float* act      = (const float*)d_in[3];
    const float* support  = (const float*)d_in[4];
    const float* low0     = (const float*)d_in[5];
    const float* high0    = (const float*)d_in[6];
    float* out = (float*)d_out;

    c2f_kernel<<<NB, THREADS>>>(q, reward, discount, act, support, low0, high0, out);
}

// round 3
// speedup vs baseline: 1.5556x; 1.5556x over previous
#include <cuda_runtime.h>
#include <math.h>

#define LEVELS 3
#define BINS 9
#define NATOMS 51
#define ADIM 6
#define NB 4096
#define ROWS (LEVELS * ADIM * BINS)      // 162
#define SLAB (ROWS * NATOMS)             // 8262 floats per batch element
#define V_MIN_C (-10.0f)
#define V_MAX_C (10.0f)
#define DZ_C (0.4f)

#define THREADS 512
#define NWARPS (THREADS / 32)
#define CHUNKS 6                         // ceil(162/32) row-chunks per k
#define NGROUPS (NATOMS * CHUNKS)        // 306 warp work-groups

__global__ __launch_bounds__(THREADS)
void c2f_kernel(const float* __restrict__ q,
                const float* __restrict__ reward,
                const float* __restrict__ discount,
                const float* __restrict__ act,
                const float* __restrict__ support,
                const float* __restrict__ low0,
                const float* __restrict__ high0,
                float* __restrict__ out)
{
    const int b = blockIdx.x;
    const int t = threadIdx.x;

    extern __shared__ float dyn[];
    float* sp = dyn;            // [SLAB] staged probs
    float* so = dyn + SLAB;     // [SLAB] staged result

    __shared__ float swl[NATOMS];
    __shared__ float swu[NATOMS];
    __shared__ int   slower[NATOMS];
    __shared__ int   sstart[NATOMS + 1];

    // ---- Phase 0: coalesced stage of slab (float2) ----
    {
        const float2* src2 = reinterpret_cast<const float2*>(q + (size_t)b * SLAB);
        float2* sp2 = reinterpret_cast<float2*>(sp);
        #pragma unroll 4
        for (int i = t; i < SLAB / 2; i += THREADS) sp2[i] = src2[i];
    }

    // ---- Phase 1a: per-atom projection coefficients ----
    if (t < NATOMS) {
        const float r = reward[b];
        const float d = discount[b];
        const float z = support[t];
        float Tz = fminf(fmaxf(r + d * z, V_MIN_C), V_MAX_C);
        float bc = (Tz - V_MIN_C) / DZ_C;
        int lo = (int)floorf(bc);
        int up = (int)ceilf(bc);
        if (up > 0 && lo == up) lo -= 1;                 // reference fixup 1
        if (lo < NATOMS - 1 && lo == up) up += 1;        // reference fixup 2 (=> up==lo+1)
        slower[t] = lo;
        swl[t] = (float)up - bc;   // mass -> atom lo
        swu[t] = bc - (float)lo;   // mass -> atom lo+1
    }

    // ---- Phase 1b: encode + decode (6 dims, in a different warp) ----
    if (t >= 64 && t < 64 + ADIM) {
        const int dim = t - 64;
        const float a = act[b * ADIM + dim];
        float low = low0[dim], high = high0[dim];
        float idx[LEVELS];
        #pragma unroll
        for (int lvl = 0; lvl < LEVELS; lvl++) {
            float sr = (high - low) / (float)BINS;
            float id = floorf((a - low) / sr);
            id = fminf(fmaxf(id, 0.0f), (float)(BINS - 1));
            float na = fminf(fmaxf(low + sr * id, -1.0f), 1.0f);
            low  = fmaxf(-1.0f, na);
            high = fminf(1.0f, na + sr);
            idx[lvl] = id;
        }
        low = low0[dim]; high = high0[dim];
        #pragma unroll
        for (int lvl = 0; lvl < LEVELS; lvl++) {
            float sr = (high - low) / (float)BINS;
            float cont = low + sr * idx[lvl];
            low  = fmaxf(-1.0f, cont);
            high = fminf(1.0f, cont + sr);
        }
        out[(size_t)NB * SLAB + (size_t)b * ADIM + dim] = 0.5f * (high + low);
    }
    __syncthreads();

    // ---- Phase 1c: range table (lower[] nondecreasing since discount >= 0) ----
    if (t < NATOMS + 1) {
        int cnt = 0;
        for (int j = 0; j < NATOMS; j++) cnt += (slower[j] < t) ? 1 : 0;
        sstart[t] = cnt;
    }
    __syncthreads();

    // ---- Phase 2: k-major gather. One warp = one k over 32 rows -> warp-uniform
    //      loop bounds, zero divergence. Stride-51 smem = conflict-free (odd).
    {
        const int warp = t >> 5;
        const int lane = t & 31;
        for (int g = warp; g < NGROUPS; g += NWARPS) {
            const int k = g / CHUNKS;
            const int row = (g - k * CHUNKS) * 32 + lane;
            const int s0 = sstart[k];
            const int s1 = sstart[k + 1];
            const int sm1 = (k > 0) ? sstart[k - 1] : s0;
            const float* pr = sp + row * NATOMS;
            float acc = 0.0f;
            const bool active = (row < ROWS);
            for (int j = s0; j < s1; j++)
                acc = fmaf(active ? pr[j] : 0.0f, swl[j], acc);
            for (int j = sm1; j < s0; j++)
                acc = fmaf(active ? pr[j] : 0.0f, swu[j], acc);
            if (active) so[row * NATOMS + k] = acc;
        }
    }
    __syncthreads();

    // ---- Phase 3: coalesced copy smem result -> global (float2) ----
    {
        const float2* so2 = reinterpret_cast<const float2*>(so);
        float2* dst2 = reinterpret_cast<float2*>(out + (size_t)b * SLAB);
        #pragma unroll 4
        for (int i = t; i < SLAB / 2; i += THREADS) dst2[i] = so2[i];
    }
}

extern "C" void kernel_launch(void* const* d_in, const int* in_sizes, int n_in,
                              void* d_out, int out_size)
{
    const float* q        = (const float*)d_in[0];
    const float* reward   = (const float*)d_in[1];
    const float* discount = (const float*)d_in[2];
    const float* act      = (const float*)d_in[3];
    const float* support  = (const float*)d_in[4];
    const float* low0     = (const float*)d_in[5];
    const float* high0    = (const float*)d_in[6];
    float* out = (float*)d_out;

    const int smem_bytes = 2 * SLAB * (int)sizeof(float);   // 66096 B
    cudaFuncSetAttribute(c2f_kernel, cudaFuncAttributeMaxDynamicSharedMemorySize,
                         smem_bytes);
    c2f_kernel<<<NB, THREADS, smem_bytes>>>(q, reward, discount, act, support,
                                            low0, high0, out);
}

// round 4
// speedup vs baseline: 2.2187x; 1.4263x over previous
#include <cuda_runtime.h>
#include <math.h>

#define LEVELS 3
#define BINS 9
#define NATOMS 51
#define ADIM 6
#define NB 4096
#define ROWS (LEVELS * ADIM * BINS)      // 162
#define SLAB (ROWS * NATOMS)             // 8262 floats per batch element
#define V_MIN_C (-10.0f)
#define V_MAX_C (10.0f)
#define DZ_C (0.4f)

#define THREADS 512

__global__ __launch_bounds__(THREADS)
void c2f_kernel(const float* __restrict__ q,
                const float* __restrict__ reward,
                const float* __restrict__ discount,
                const float* __restrict__ act,
                const float* __restrict__ support,
                const float* __restrict__ low0,
                const float* __restrict__ high0,
                float* __restrict__ out)
{
    const int b = blockIdx.x;
    const int t = threadIdx.x;

    extern __shared__ float dyn[];
    float* sp = dyn;            // [SLAB] staged probs
    float* so = dyn + SLAB;     // [SLAB] staged result (pre-zeroed)

    __shared__ float swl[NATOMS];
    __shared__ float swu[NATOMS];
    __shared__ int   slower[NATOMS];

    // ---- Phase 0: coalesced stage of slab + zero result slab (fused loop) ----
    {
        const float2* src2 = reinterpret_cast<const float2*>(q + (size_t)b * SLAB);
        float2* sp2 = reinterpret_cast<float2*>(sp);
        float2* so2 = reinterpret_cast<float2*>(so);
        const float2 z2 = make_float2(0.0f, 0.0f);
        #pragma unroll 4
        for (int i = t; i < SLAB / 2; i += THREADS) { sp2[i] = src2[i]; so2[i] = z2; }
    }

    // ---- Phase 1a: per-atom projection coefficients (block-uniform tables) ----
    if (t < NATOMS) {
        const float r = reward[b];
        const float d = discount[b];
        const float z = support[t];
        float Tz = fminf(fmaxf(r + d * z, V_MIN_C), V_MAX_C);
        float bc = (Tz - V_MIN_C) / DZ_C;
        int lo = (int)floorf(bc);
        int up = (int)ceilf(bc);
        if (up > 0 && lo == up) lo -= 1;                 // reference fixup 1
        if (lo < NATOMS - 1 && lo == up) up += 1;        // reference fixup 2 (=> up==lo+1)
        slower[t] = lo;                                  // lo in [0, 49]
        swl[t] = (float)up - bc;   // mass -> atom lo
        swu[t] = bc - (float)lo;   // mass -> atom lo+1
    }

    // ---- Phase 1b: encode + decode (6 dims, separate warp) ----
    if (t >= 64 && t < 64 + ADIM) {
        const int dim = t - 64;
        const float a = act[b * ADIM + dim];
        float low = low0[dim], high = high0[dim];
        float idx[LEVELS];
        #pragma unroll
        for (int lvl = 0; lvl < LEVELS; lvl++) {
            float sr = (high - low) / (float)BINS;
            float id = floorf((a - low) / sr);
            id = fminf(fmaxf(id, 0.0f), (float)(BINS - 1));
            float na = fminf(fmaxf(low + sr * id, -1.0f), 1.0f);
            low  = fmaxf(-1.0f, na);
            high = fminf(1.0f, na + sr);
            idx[lvl] = id;
        }
        low = low0[dim]; high = high0[dim];
        #pragma unroll
        for (int lvl = 0; lvl < LEVELS; lvl++) {
            float sr = (high - low) / (float)BINS;
            float cont = low + sr * idx[lvl];
            low  = fmaxf(-1.0f, cont);
            high = fminf(1.0f, cont + sr);
        }
        out[(size_t)NB * SLAB + (size_t)b * ADIM + dim] = 0.5f * (high + low);
    }
    __syncthreads();

    // ---- Phase 2: one thread per row, single sequential walk over j=0..50.
    //      lower[] is block-uniform and nondecreasing -> all branches uniform.
    //      m[k] = A_k + B_{k-1};  A/B accumulated per group, B carried forward.
    if (t < ROWS) {
        const float* pr = sp + t * NATOMS;   // lane stride 51 (odd) -> conflict-free
        float* po = so + t * NATOMS;
        int kcur = slower[0];
        float accA = 0.0f, accB = 0.0f, carryB = 0.0f;
        #pragma unroll 1
        for (int j = 0; j < NATOMS; j++) {
            const int kj = slower[j];        // uniform LDS broadcast
            if (kj != kcur) {                // uniform branch
                po[kcur] = accA + carryB;
                if (kj == kcur + 1) {
                    carryB = accB;
                } else {                     // gap: B lands alone at kcur+1
                    po[kcur + 1] = accB;
                    carryB = 0.0f;
                }
                accA = 0.0f; accB = 0.0f; kcur = kj;
            }
            const float p = pr[j];
            accA = fmaf(p, swl[j], accA);
            accB = fmaf(p, swu[j], accB);
        }
        po[kcur] = accA + carryB;
        po[kcur + 1] = accB;                 // kcur <= 49, index <= 50 safe
    }
    __syncthreads();

    // ---- Phase 3: coalesced copy smem result -> global (float2) ----
    {
        const float2* so2 = reinterpret_cast<const float2*>(so);
        float2* dst2 = reinterpret_cast<float2*>(out + (size_t)b * SLAB);
        #pragma unroll 4
        for (int i = t; i < SLAB / 2; i += THREADS) dst2[i] = so2[i];
    }
}

extern "C" void kernel_launch(void* const* d_in, const int* in_sizes, int n_in,
                              void* d_out, int out_size)
{
    const float* q        = (const float*)d_in[0];
    const float* reward   = (const float*)d_in[1];
    const float* discount = (const float*)d_in[2];
    const float* act      = (const float*)d_in[3];
    const float* support  = (const float*)d_in[4];
    const float* low0     = (const float*)d_in[5];
    const float* high0    = (const float*)d_in[6];
    float* out = (float*)d_out;

    const int smem_bytes = 2 * SLAB * (int)sizeof(float);   // 66096 B
    cudaFuncSetAttribute(c2f_kernel, cudaFuncAttributeMaxDynamicSharedMemorySize,
                         smem_bytes);
    c2f_kernel<<<NB, THREADS, smem_bytes>>>(q, reward, discount, act, support,
                                            low0, high0, out);
}